// round 10
// baseline (speedup 1.0000x reference)
#include <cuda_runtime.h>
#include <math.h>
#include <stdint.h>

// Problem constants
#define S_LEN   256
#define B_SZ    64
#define E_DIM   300
#define H2_DIM  256
#define H_DIM   512
#define T_TAGS  10
#define START_TAG 8
#define STOP_TAG  9
#define NTOK    (S_LEN * B_SZ)     // 16384
#define G4      (4 * H2_DIM)       // 1024

#define LSTM_BLOCKS 128

typedef unsigned long long ull;

// ---------- packed f32x2 helpers (exact fp32, 2x FMA-pipe throughput) ------
__device__ __forceinline__ ull pk2(float x, float y) {
    ull r;
    asm("mov.b64 %0, {%1, %2};" : "=l"(r) : "f"(x), "f"(y));
    return r;
}
__device__ __forceinline__ void fma2(ull& c, ull a, ull b) {
    asm("fma.rn.f32x2 %0, %1, %2, %0;" : "+l"(c) : "l"(a), "l"(b));
}
__device__ __forceinline__ float2 up2(ull v) {
    float2 r;
    asm("mov.b64 {%0, %1}, %2;" : "=f"(r.x), "=f"(r.y) : "l"(v));
    return r;
}

// ---------------- scratch (device globals; no allocation allowed) ----------
__device__ __align__(16) float d_G[2][NTOK][G4];        // gate preactivations (x part + biases)
__device__ __align__(16) float d_Hout[NTOK][H_DIM];     // concatenated hidden states (S*B, 512)
__device__ __align__(16) float d_feats[NTOK][T_TAGS];   // emission scores
__device__ __align__(16) float d_hstate[2][2][B_SZ][H2_DIM]; // [parity][dir][b][h]
__device__ unsigned int d_bar_arrive;
__device__ volatile unsigned int d_bar_release;

// ---------------- init: reset barrier state + seed h0 ----------------------
__global__ void init_kernel(const float* __restrict__ h0) {
    if (blockIdx.x == 0 && threadIdx.x == 0) {
        d_bar_arrive = 0u;
        d_bar_release = 0u;
    }
    int idx = blockIdx.x * blockDim.x + threadIdx.x;
    float* dst = &d_hstate[0][0][0][0];     // parity 0, both dirs: layout matches h0 (2,B,H2)
    for (int i = idx; i < 2 * B_SZ * H2_DIM; i += gridDim.x * blockDim.x)
        dst[i] = h0[i];
}

// ---------------- input GEMM: G = gather(emb, tok) @ wih^T + bih + bhh -----
// M=16384 (64-tile), N=1024 (64-tile), K=300 (12-tile, 25 iters exact)
__global__ __launch_bounds__(256) void input_gemm_kernel(
    const int*   __restrict__ sent,
    const float* __restrict__ emb,
    const float* __restrict__ wih_f, const float* __restrict__ bih_f, const float* __restrict__ bhh_f,
    const float* __restrict__ wih_b, const float* __restrict__ bih_b, const float* __restrict__ bhh_b)
{
    const int dir = blockIdx.z;
    const float* wih = dir ? wih_b : wih_f;
    const float* bih = dir ? bih_b : bih_f;
    const float* bhh = dir ? bhh_b : bhh_f;
    float* Gout = &d_G[dir][0][0];

    __shared__ __align__(16) float As[12][64];
    __shared__ __align__(16) float Bs[12][64];
    __shared__ int toks[64];

    const int tid = threadIdx.x;
    const int n0 = blockIdx.x * 64;
    const int j0 = blockIdx.y * 64;

    if (tid < 64) toks[tid] = sent[n0 + tid];
    __syncthreads();

    const int tx = tid & 15;        // j quad
    const int ty = tid >> 4;        // n quad
    ull acc[4][2];                  // [row i][col pair] packed f32x2
#pragma unroll
    for (int i = 0; i < 4; ++i) { acc[i][0] = 0ull; acc[i][1] = 0ull; }

    for (int k0 = 0; k0 < E_DIM; k0 += 12) {
#pragma unroll
        for (int i = 0; i < 3; ++i) {
            int idx = i * 256 + tid;            // 0..767 = 64 rows * 12 k
            int nn = idx / 12, kk = idx % 12;
            As[kk][nn] = emb[(size_t)toks[nn] * E_DIM + k0 + kk];
            Bs[kk][nn] = wih[(size_t)(j0 + nn) * E_DIM + k0 + kk];
        }
        __syncthreads();
#pragma unroll
        for (int kk = 0; kk < 12; ++kk) {
            float4 a = *(const float4*)&As[kk][ty * 4];
            ulonglong2 bv = *(const ulonglong2*)&Bs[kk][tx * 4];
            ull pa0 = pk2(a.x, a.x);
            ull pa1 = pk2(a.y, a.y);
            ull pa2 = pk2(a.z, a.z);
            ull pa3 = pk2(a.w, a.w);
            fma2(acc[0][0], pa0, bv.x); fma2(acc[0][1], pa0, bv.y);
            fma2(acc[1][0], pa1, bv.x); fma2(acc[1][1], pa1, bv.y);
            fma2(acc[2][0], pa2, bv.x); fma2(acc[2][1], pa2, bv.y);
            fma2(acc[3][0], pa3, bv.x); fma2(acc[3][1], pa3, bv.y);
        }
        __syncthreads();
    }

    float4 bi = *(const float4*)&bih[j0 + tx * 4];
    float4 bh = *(const float4*)&bhh[j0 + tx * 4];
    float bs0 = bi.x + bh.x, bs1 = bi.y + bh.y, bs2 = bi.z + bh.z, bs3 = bi.w + bh.w;
#pragma unroll
    for (int ii = 0; ii < 4; ++ii) {
        int n = n0 + ty * 4 + ii;
        float2 lo = up2(acc[ii][0]);
        float2 hi = up2(acc[ii][1]);
        float4 o = make_float4(lo.x + bs0, lo.y + bs1, hi.x + bs2, hi.y + bs3);
        *(float4*)&Gout[(size_t)n * G4 + j0 + tx * 4] = o;
    }
}

// ---------------- grid barrier (counter + generation) -----------------------
__device__ __forceinline__ void grid_barrier(unsigned int gen) {
    __syncthreads();
    if (threadIdx.x == 0) {
        __threadfence();
        unsigned int t = atomicAdd(&d_bar_arrive, 1u);
        if (t == LSTM_BLOCKS - 1) {
            atomicExch(&d_bar_arrive, 0u);
            __threadfence();
            d_bar_release = gen;
        } else {
            while (d_bar_release < gen) { }
            __threadfence();
        }
    }
    __syncthreads();
}

// ---------------- persistent bidirectional LSTM -----------------------------
// 128 blocks x 128 threads: dir = bid>>6; slice = bid&63 -> batch half (32 b)
// x hidden seg (8 h-units = 32 gate rows). Packed-f32x2 inner loop, balanced
// at ~2048 cyc/step on fma/LSU/issue; h-chunk staging register-prefetched.
__global__ __launch_bounds__(128, 1) void lstm_kernel(
    const float* __restrict__ whh_f,
    const float* __restrict__ whh_b,
    const float* __restrict__ c0)
{
    const int dir   = blockIdx.x >> 6;
    const int slice = blockIdx.x & 63;
    const int bh    = slice >> 5;     // 0/1 batch half
    const int hseg  = slice & 31;     // hidden segment (8 units -> 32 gate rows)
    const int bbase = bh * 32;
    const int tid   = threadIdx.x;

    // Ws4[k2][rp] = (w[2k2][2rp], w[2k2][2rp+1], w[2k2+1][2rp], w[2k2+1][2rp+1])
    __shared__ __align__(16) float4 Ws4[128][16];   // 32 KB (whole Whh slice)
    // Hsv[k2][bp] = (h[2k2][2bp], h[2k2][2bp+1], h[2k2+1][2bp], h[2k2+1][2bp+1])
    __shared__ __align__(16) float4 Hsv[32][16];    // 8 KB (one 64-k chunk)
    __shared__ float Gsm[32][33];                   // gate exchange [b_local][r]

    const float* whh = dir ? whh_b : whh_f;
    const float* Gin = &d_G[dir][0][0];

    // Build Ws4 once (2048 float4 entries, 16 per thread)
    for (int i = tid; i < 128 * 16; i += 128) {
        int k2 = i >> 4, rp = i & 15;
        int r0 = 2 * rp, r1 = r0 + 1;
        int rg0 = (r0 >> 3) * H2_DIM + hseg * 8 + (r0 & 7);
        int rg1 = (r1 >> 3) * H2_DIM + hseg * 8 + (r1 & 7);
        Ws4[k2][rp] = make_float4(whh[(size_t)rg0 * H2_DIM + 2 * k2],
                                  whh[(size_t)rg1 * H2_DIM + 2 * k2],
                                  whh[(size_t)rg0 * H2_DIM + 2 * k2 + 1],
                                  whh[(size_t)rg1 * H2_DIM + 2 * k2 + 1]);
    }

    // GEMM ownership: thread -> rows (r0, r0+1) x batches (4ty .. 4ty+3)
    const int tx = tid & 15, ty = tid >> 4;
    const int r0 = 2 * tx;
    const int rg0 = (r0 >> 3) * H2_DIM + hseg * 8 + (r0 & 7);  // rg1 = rg0+1
    const int bp0 = 2 * ty, bp1 = 2 * ty + 1;

    // staging ownership: thread -> batch (tid&31), k quarter (tid>>5)
    const int stg_b  = tid & 31;
    const int stg_jq = tid >> 5;          // 0..3
    const int kbase0 = stg_jq * 16;
    const int stg_bp = stg_b >> 1;
    const int stg_c  = stg_b & 1;

    // pointwise ownership: thread -> (b = tid>>3, hh = tid&7) and (b+16, hh)
    const int bq0 = tid >> 3, hh = tid & 7;
    const int hidx = hseg * 8 + hh;
    float c_0 = c0[dir * B_SZ * H2_DIM + (bbase + bq0) * H2_DIM + hidx];
    float c_1 = c0[dir * B_SZ * H2_DIM + (bbase + bq0 + 16) * H2_DIM + hidx];

    __syncthreads();

    for (int it = 0; it < S_LEN; ++it) {
        const int s = dir ? (S_LEN - 1 - it) : it;
        const int p = it & 1;
        const float* hprev = &d_hstate[p][dir][0][0];
        float* hnext = &d_hstate[p ^ 1][dir][0][0];
        const float* hp = &hprev[(bbase + stg_b) * H2_DIM];

        // G loads for this step (independent of barrier state)
        float2 gv[4];
#pragma unroll
        for (int u = 0; u < 4; ++u)
            gv[u] = *(const float2*)&Gin[(size_t)(s * B_SZ + bbase + 4 * ty + u) * G4 + rg0];

        // prefetch chunk 0 of hprev
        float4 pf[4];
#pragma unroll
        for (int u = 0; u < 4; ++u)
            pf[u] = __ldcg((const float4*)&hp[kbase0 + 4 * u]);

        ull a00 = 0ull, a01 = 0ull, a10 = 0ull, a11 = 0ull;
        // a00: row r0, batches (4ty,4ty+1); a10: row r0+1, same
        // a01: row r0, batches (4ty+2,4ty+3); a11: row r0+1, same

#pragma unroll 1
        for (int c = 0; c < 4; ++c) {
            // store prefetched chunk c into Hsv
#pragma unroll
            for (int u = 0; u < 4; ++u) {
                int kl = kbase0 + 4 * u;          // multiple of 4
                int k2l = kl >> 1;                // even
                float* t0 = &Hsv[k2l][stg_bp].x;
                t0[stg_c] = pf[u].x; t0[2 + stg_c] = pf[u].y;
                float* t1 = &Hsv[k2l + 1][stg_bp].x;
                t1[stg_c] = pf[u].z; t1[2 + stg_c] = pf[u].w;
            }
            // prefetch chunk c+1 (consumed next iteration; latency hidden by compute)
            if (c < 3) {
#pragma unroll
                for (int u = 0; u < 4; ++u)
                    pf[u] = __ldcg((const float4*)&hp[(c + 1) * 64 + kbase0 + 4 * u]);
            }
            __syncthreads();

#pragma unroll 8
            for (int k2l = 0; k2l < 32; ++k2l) {
                float4 wq = Ws4[c * 32 + k2l][tx];
                ulonglong2 h0 = *(const ulonglong2*)&Hsv[k2l][bp0];
                ulonglong2 h1 = *(const ulonglong2*)&Hsv[k2l][bp1];
                ull w00 = pk2(wq.x, wq.x);   // k even, row r0
                ull w01 = pk2(wq.y, wq.y);   // k even, row r0+1
                ull w10 = pk2(wq.z, wq.z);   // k odd,  row r0
                ull w11 = pk2(wq.w, wq.w);   // k odd,  row r0+1
                fma2(a00, h0.x, w00); fma2(a10, h0.x, w01);
                fma2(a00, h0.y, w10); fma2(a10, h0.y, w11);
                fma2(a01, h1.x, w00); fma2(a11, h1.x, w01);
                fma2(a01, h1.y, w10); fma2(a11, h1.y, w11);
            }
            __syncthreads();
        }

        // write gates to exchange buffer (+ x-part from G)
        {
            float2 u00 = up2(a00), u10 = up2(a10), u01 = up2(a01), u11 = up2(a11);
            int b0 = 4 * ty;
            Gsm[b0 + 0][r0]     = u00.x + gv[0].x;
            Gsm[b0 + 0][r0 + 1] = u10.x + gv[0].y;
            Gsm[b0 + 1][r0]     = u00.y + gv[1].x;
            Gsm[b0 + 1][r0 + 1] = u10.y + gv[1].y;
            Gsm[b0 + 2][r0]     = u01.x + gv[2].x;
            Gsm[b0 + 2][r0 + 1] = u11.x + gv[2].y;
            Gsm[b0 + 3][r0]     = u01.y + gv[3].x;
            Gsm[b0 + 3][r0 + 1] = u11.y + gv[3].y;
        }
        __syncthreads();

        // pointwise: two (b,h) pairs per thread
        {
            float gi = Gsm[bq0][hh], gf = Gsm[bq0][8 + hh];
            float gg = Gsm[bq0][16 + hh], go = Gsm[bq0][24 + hh];
            float si = 1.f / (1.f + expf(-gi));
            float sf = 1.f / (1.f + expf(-gf));
            float so = 1.f / (1.f + expf(-go));
            c_0 = sf * c_0 + si * tanhf(gg);
            float h = so * tanhf(c_0);
            __stcg(&hnext[(bbase + bq0) * H2_DIM + hidx], h);
            d_Hout[s * B_SZ + bbase + bq0][dir * H2_DIM + hidx] = h;
        }
        {
            int b1 = bq0 + 16;
            float gi = Gsm[b1][hh], gf = Gsm[b1][8 + hh];
            float gg = Gsm[b1][16 + hh], go = Gsm[b1][24 + hh];
            float si = 1.f / (1.f + expf(-gi));
            float sf = 1.f / (1.f + expf(-gf));
            float so = 1.f / (1.f + expf(-go));
            c_1 = sf * c_1 + si * tanhf(gg);
            float h = so * tanhf(c_1);
            __stcg(&hnext[(bbase + b1) * H2_DIM + hidx], h);
            d_Hout[s * B_SZ + bbase + b1][dir * H2_DIM + hidx] = h;
        }

        if (it < S_LEN - 1)
            grid_barrier((unsigned int)(it + 1));
    }
}

// ---------------- feats: (16384 x 512) @ (512 x 10) + b ---------------------
__global__ __launch_bounds__(256) void feats_kernel(
    const float* __restrict__ W_out, const float* __restrict__ b_out)
{
    const int warp = threadIdx.x >> 5;
    const int lane = threadIdx.x & 31;
    const int n = blockIdx.x * 8 + warp;
    const float* hrow = &d_Hout[n][0];

    float acc[T_TAGS];
#pragma unroll
    for (int t = 0; t < T_TAGS; ++t) acc[t] = 0.f;

#pragma unroll
    for (int i = 0; i < 16; ++i) {
        int idx = i * 32 + lane;
        float hv = hrow[idx];
#pragma unroll
        for (int t = 0; t < T_TAGS; ++t)
            acc[t] += hv * W_out[t * H_DIM + idx];
    }
#pragma unroll
    for (int t = 0; t < T_TAGS; ++t) {
        float v = acc[t];
#pragma unroll
        for (int off = 16; off > 0; off >>= 1)
            v += __shfl_down_sync(0xffffffffu, v, off);
        if (lane == 0) d_feats[n][t] = v + b_out[t];
    }
}

// ---------------- Viterbi: one warp per batch --------------------------------
__global__ void viterbi_kernel(const float* __restrict__ trans, float* __restrict__ out) {
    const int b = blockIdx.x;
    const int lane = threadIdx.x;
    __shared__ float tr[T_TAGS][T_TAGS];
    __shared__ unsigned char bp[S_LEN][T_TAGS];

    for (int i = lane; i < T_TAGS * T_TAGS; i += 32)
        tr[i / T_TAGS][i % T_TAGS] = trans[i];
    __syncwarp();

    const int ln = lane < T_TAGS ? lane : 0;   // safe index for lanes >= 10
    float fv = (lane == START_TAG) ? 0.f : -10000.f;

    for (int s = 0; s < S_LEN; ++s) {
        float best = -3.4e38f;
        int arg = 0;
#pragma unroll
        for (int pv = 0; pv < T_TAGS; ++pv) {
            float fp = __shfl_sync(0xffffffffu, fv, pv);
            float v = fp + tr[ln][pv];
            if (v > best) { best = v; arg = pv; }   // strict > keeps FIRST max (jnp.argmax)
        }
        if (lane < T_TAGS) bp[s][lane] = (unsigned char)arg;
        fv = best + d_feats[b * S_LEN + s][ln];
        __syncwarp();
    }

    float term = fv + tr[STOP_TAG][ln];
    __syncwarp();

    float bestv = -3.4e38f;
    int bestt = 0;
#pragma unroll
    for (int t = 0; t < T_TAGS; ++t) {
        float v = __shfl_sync(0xffffffffu, term, t);
        if (v > bestv) { bestv = v; bestt = t; }
    }

    if (lane == 0) {
        out[b] = bestv;                      // path_score (B,1)
        float* pathout = out + B_SZ + b * S_LEN;
        int cur = bestt;
        pathout[S_LEN - 1] = (float)cur;
        for (int s = S_LEN - 2; s >= 0; --s) {
            cur = bp[s + 1][cur];
            pathout[s] = (float)cur;
        }
    }
}

// ---------------- launch ------------------------------------------------------
extern "C" void kernel_launch(void* const* d_in, const int* in_sizes, int n_in,
                              void* d_out, int out_size) {
    const int*   sent  = (const int*)  d_in[0];
    const float* emb   = (const float*)d_in[1];
    const float* wih_f = (const float*)d_in[2];
    const float* whh_f = (const float*)d_in[3];
    const float* bih_f = (const float*)d_in[4];
    const float* bhh_f = (const float*)d_in[5];
    const float* wih_b = (const float*)d_in[6];
    const float* whh_b = (const float*)d_in[7];
    const float* bih_b = (const float*)d_in[8];
    const float* bhh_b = (const float*)d_in[9];
    const float* W_out = (const float*)d_in[10];
    const float* b_out = (const float*)d_in[11];

    // Resolve trailing-argument order at runtime (transitions = 100 elems).
    const float *trans, *h0, *c0;
    if (n_in >= 15 && in_sizes[12] == 100) {
        trans = (const float*)d_in[12];
        h0    = (const float*)d_in[13];
        c0    = (const float*)d_in[14];
    } else {
        h0    = (const float*)d_in[12];
        c0    = (const float*)d_in[13];
        trans = (const float*)d_in[14];
    }

    float* out = (float*)d_out;

    init_kernel<<<32, 256>>>(h0);
    dim3 g(NTOK / 64, G4 / 64, 2);   // 256 x 16 x 2
    input_gemm_kernel<<<g, 256>>>(sent, emb, wih_f, bih_f, bhh_f, wih_b, bih_b, bhh_b);
    lstm_kernel<<<LSTM_BLOCKS, 128>>>(whh_f, whh_b, c0);
    feats_kernel<<<NTOK / 8, 256>>>(W_out, b_out);
    viterbi_kernel<<<B_SZ, 32>>>(trans, out);
    (void)out_size; (void)n_in;
}

// round 11
// speedup vs baseline: 1.1198x; 1.1198x over previous
#include <cuda_runtime.h>
#include <math.h>
#include <stdint.h>

// Problem constants
#define S_LEN   256
#define B_SZ    64
#define E_DIM   300
#define H2_DIM  256
#define H_DIM   512
#define T_TAGS  10
#define START_TAG 8
#define STOP_TAG  9
#define NTOK    (S_LEN * B_SZ)     // 16384
#define G4      (4 * H2_DIM)       // 1024

#define LSTM_BLOCKS 128
#define GROUP_BLOCKS 32            // blocks per (dir, batch-half) barrier group

typedef unsigned long long ull;

// ---------- packed f32x2 helpers (exact fp32, 2x FMA-pipe throughput) ------
__device__ __forceinline__ ull pk2(float x, float y) {
    ull r;
    asm("mov.b64 %0, {%1, %2};" : "=l"(r) : "f"(x), "f"(y));
    return r;
}
__device__ __forceinline__ void fma2(ull& c, ull a, ull b) {
    asm("fma.rn.f32x2 %0, %1, %2, %0;" : "+l"(c) : "l"(a), "l"(b));
}
__device__ __forceinline__ float2 up2(ull v) {
    float2 r;
    asm("mov.b64 {%0, %1}, %2;" : "=f"(r.x), "=f"(r.y) : "l"(v));
    return r;
}

// ---------------- scratch (device globals; no allocation allowed) ----------
__device__ __align__(16) float d_G[2][NTOK][G4];        // gate preactivations (x part + biases)
__device__ __align__(16) float d_Hout[NTOK][H_DIM];     // concatenated hidden states (S*B, 512)
__device__ __align__(16) float d_feats[NTOK][T_TAGS];   // emission scores
__device__ __align__(16) float d_hstate[2][2][B_SZ][H2_DIM]; // [parity][dir][b][h]
// 4 monotonic barrier counters, each on its own 128B line (zero-initialized .bss;
// reset to 0 by viterbi_kernel each call so graph replays are deterministic)
__device__ unsigned int d_cnt[4 * 32];

// ---------- group barrier primitives (release-red arrive, acquire poll) ----
__device__ __forceinline__ void bar_arrive(unsigned int* c) {
    asm volatile("red.release.gpu.global.add.u32 [%0], 1;" :: "l"(c) : "memory");
}
__device__ __forceinline__ unsigned int bar_ld_acq(const unsigned int* c) {
    unsigned int v;
    asm volatile("ld.acquire.gpu.global.u32 %0, [%1];" : "=r"(v) : "l"(c) : "memory");
    return v;
}

// ---------------- input GEMM: G = gather(emb, tok) @ wih^T + bih + bhh -----
// M=16384 (64-tile), N=1024 (64-tile), K=300 (12-tile, 25 iters exact)
// Block (0,0,0) additionally seeds d_hstate[0] from h0 (init kernel folded in).
__global__ __launch_bounds__(256) void input_gemm_kernel(
    const int*   __restrict__ sent,
    const float* __restrict__ emb,
    const float* __restrict__ wih_f, const float* __restrict__ bih_f, const float* __restrict__ bhh_f,
    const float* __restrict__ wih_b, const float* __restrict__ bih_b, const float* __restrict__ bhh_b,
    const float* __restrict__ h0)
{
    const int dir = blockIdx.z;
    const float* wih = dir ? wih_b : wih_f;
    const float* bih = dir ? bih_b : bih_f;
    const float* bhh = dir ? bhh_b : bhh_f;
    float* Gout = &d_G[dir][0][0];

    __shared__ __align__(16) float As[12][64];
    __shared__ __align__(16) float Bs[12][64];
    __shared__ int toks[64];

    const int tid = threadIdx.x;
    const int n0 = blockIdx.x * 64;
    const int j0 = blockIdx.y * 64;

    // folded init: copy h0 -> d_hstate parity 0 (layout (2,B,H2) matches)
    if (blockIdx.x == 0 && blockIdx.y == 0 && blockIdx.z == 0) {
        float* dst = &d_hstate[0][0][0][0];
        for (int i = tid; i < 2 * B_SZ * H2_DIM; i += 256)
            dst[i] = h0[i];
    }

    if (tid < 64) toks[tid] = sent[n0 + tid];
    __syncthreads();

    const int tx = tid & 15;        // j quad
    const int ty = tid >> 4;        // n quad
    ull acc[4][2];                  // [row i][col pair] packed f32x2
#pragma unroll
    for (int i = 0; i < 4; ++i) { acc[i][0] = 0ull; acc[i][1] = 0ull; }

    for (int k0 = 0; k0 < E_DIM; k0 += 12) {
#pragma unroll
        for (int i = 0; i < 3; ++i) {
            int idx = i * 256 + tid;            // 0..767 = 64 rows * 12 k
            int nn = idx / 12, kk = idx % 12;
            As[kk][nn] = emb[(size_t)toks[nn] * E_DIM + k0 + kk];
            Bs[kk][nn] = wih[(size_t)(j0 + nn) * E_DIM + k0 + kk];
        }
        __syncthreads();
#pragma unroll
        for (int kk = 0; kk < 12; ++kk) {
            float4 a = *(const float4*)&As[kk][ty * 4];
            ulonglong2 bv = *(const ulonglong2*)&Bs[kk][tx * 4];
            ull pa0 = pk2(a.x, a.x);
            ull pa1 = pk2(a.y, a.y);
            ull pa2 = pk2(a.z, a.z);
            ull pa3 = pk2(a.w, a.w);
            fma2(acc[0][0], pa0, bv.x); fma2(acc[0][1], pa0, bv.y);
            fma2(acc[1][0], pa1, bv.x); fma2(acc[1][1], pa1, bv.y);
            fma2(acc[2][0], pa2, bv.x); fma2(acc[2][1], pa2, bv.y);
            fma2(acc[3][0], pa3, bv.x); fma2(acc[3][1], pa3, bv.y);
        }
        __syncthreads();
    }

    float4 bi = *(const float4*)&bih[j0 + tx * 4];
    float4 bh = *(const float4*)&bhh[j0 + tx * 4];
    float bs0 = bi.x + bh.x, bs1 = bi.y + bh.y, bs2 = bi.z + bh.z, bs3 = bi.w + bh.w;
#pragma unroll
    for (int ii = 0; ii < 4; ++ii) {
        int n = n0 + ty * 4 + ii;
        float2 lo = up2(acc[ii][0]);
        float2 hi = up2(acc[ii][1]);
        float4 o = make_float4(lo.x + bs0, lo.y + bs1, hi.x + bs2, hi.y + bs3);
        *(float4*)&Gout[(size_t)n * G4 + j0 + tx * 4] = o;
    }
}

// ---------------- persistent bidirectional LSTM -----------------------------
// 128 blocks x 128 threads: dir = bid>>6; slice = bid&63 -> batch half (32 b)
// x hidden seg (8 h-units = 32 gate rows). Packed-f32x2 inner loop.
// Barrier: 4 independent groups (dir x batch-half), 32 arrivals each, monotonic
// counter with release-red arrive / acquire-load poll (no MEMBAR, no reset).
__global__ __launch_bounds__(128, 1) void lstm_kernel(
    const float* __restrict__ whh_f,
    const float* __restrict__ whh_b,
    const float* __restrict__ c0)
{
    const int dir   = blockIdx.x >> 6;
    const int slice = blockIdx.x & 63;
    const int bh    = slice >> 5;     // 0/1 batch half
    const int hseg  = slice & 31;     // hidden segment (8 units -> 32 gate rows)
    const int bbase = bh * 32;
    const int tid   = threadIdx.x;
    unsigned int* grp_cnt = &d_cnt[(blockIdx.x >> 5) * 32];  // group id = dir*2+bh

    // Ws4[k2][rp] = (w[2k2][2rp], w[2k2][2rp+1], w[2k2+1][2rp], w[2k2+1][2rp+1])
    __shared__ __align__(16) float4 Ws4[128][16];   // 32 KB (whole Whh slice)
    // Hsv[k2][bp] = (h[2k2][2bp], h[2k2][2bp+1], h[2k2+1][2bp], h[2k2+1][2bp+1])
    __shared__ __align__(16) float4 Hsv[32][16];    // 8 KB (one 64-k chunk)
    __shared__ float Gsm[32][33];                   // gate exchange [b_local][r]

    const float* whh = dir ? whh_b : whh_f;
    const float* Gin = &d_G[dir][0][0];

    // Build Ws4 once (2048 float4 entries, 16 per thread)
    for (int i = tid; i < 128 * 16; i += 128) {
        int k2 = i >> 4, rp = i & 15;
        int r0 = 2 * rp, r1 = r0 + 1;
        int rg0 = (r0 >> 3) * H2_DIM + hseg * 8 + (r0 & 7);
        int rg1 = (r1 >> 3) * H2_DIM + hseg * 8 + (r1 & 7);
        Ws4[k2][rp] = make_float4(whh[(size_t)rg0 * H2_DIM + 2 * k2],
                                  whh[(size_t)rg1 * H2_DIM + 2 * k2],
                                  whh[(size_t)rg0 * H2_DIM + 2 * k2 + 1],
                                  whh[(size_t)rg1 * H2_DIM + 2 * k2 + 1]);
    }

    // GEMM ownership: thread -> rows (r0, r0+1) x batches (4ty .. 4ty+3)
    const int tx = tid & 15, ty = tid >> 4;
    const int r0 = 2 * tx;
    const int rg0 = (r0 >> 3) * H2_DIM + hseg * 8 + (r0 & 7);  // rg1 = rg0+1
    const int bp0 = 2 * ty, bp1 = 2 * ty + 1;

    // staging ownership: thread -> batch (tid&31), k quarter (tid>>5)
    const int stg_b  = tid & 31;
    const int stg_jq = tid >> 5;          // 0..3
    const int kbase0 = stg_jq * 16;
    const int stg_bp = stg_b >> 1;
    const int stg_c  = stg_b & 1;

    // pointwise ownership: thread -> (b = tid>>3, hh = tid&7) and (b+16, hh)
    const int bq0 = tid >> 3, hh = tid & 7;
    const int hidx = hseg * 8 + hh;
    float c_0 = c0[dir * B_SZ * H2_DIM + (bbase + bq0) * H2_DIM + hidx];
    float c_1 = c0[dir * B_SZ * H2_DIM + (bbase + bq0 + 16) * H2_DIM + hidx];

    // G loads for step 0
    float2 gv[4];
    {
        const int s0 = dir ? (S_LEN - 1) : 0;
#pragma unroll
        for (int u = 0; u < 4; ++u)
            gv[u] = *(const float2*)&Gin[(size_t)(s0 * B_SZ + bbase + 4 * ty + u) * G4 + rg0];
    }

    __syncthreads();

    for (int it = 0; it < S_LEN; ++it) {
        const int s = dir ? (S_LEN - 1 - it) : it;
        const int p = it & 1;
        const float* hprev = &d_hstate[p][dir][0][0];
        float* hnext = &d_hstate[p ^ 1][dir][0][0];
        const float* hp = &hprev[(bbase + stg_b) * H2_DIM];

        // prefetch chunk 0 of hprev
        float4 pf[4];
#pragma unroll
        for (int u = 0; u < 4; ++u)
            pf[u] = __ldcg((const float4*)&hp[kbase0 + 4 * u]);

        ull a00 = 0ull, a01 = 0ull, a10 = 0ull, a11 = 0ull;

#pragma unroll 1
        for (int c = 0; c < 4; ++c) {
            // store prefetched chunk c into Hsv
#pragma unroll
            for (int u = 0; u < 4; ++u) {
                int kl = kbase0 + 4 * u;          // multiple of 4
                int k2l = kl >> 1;                // even
                float* t0 = &Hsv[k2l][stg_bp].x;
                t0[stg_c] = pf[u].x; t0[2 + stg_c] = pf[u].y;
                float* t1 = &Hsv[k2l + 1][stg_bp].x;
                t1[stg_c] = pf[u].z; t1[2 + stg_c] = pf[u].w;
            }
            // prefetch chunk c+1 (consumed next iteration; latency hidden by compute)
            if (c < 3) {
#pragma unroll
                for (int u = 0; u < 4; ++u)
                    pf[u] = __ldcg((const float4*)&hp[(c + 1) * 64 + kbase0 + 4 * u]);
            }
            __syncthreads();

#pragma unroll 8
            for (int k2l = 0; k2l < 32; ++k2l) {
                float4 wq = Ws4[c * 32 + k2l][tx];
                ulonglong2 h0 = *(const ulonglong2*)&Hsv[k2l][bp0];
                ulonglong2 h1 = *(const ulonglong2*)&Hsv[k2l][bp1];
                ull w00 = pk2(wq.x, wq.x);   // k even, row r0
                ull w01 = pk2(wq.y, wq.y);   // k even, row r0+1
                ull w10 = pk2(wq.z, wq.z);   // k odd,  row r0
                ull w11 = pk2(wq.w, wq.w);   // k odd,  row r0+1
                fma2(a00, h0.x, w00); fma2(a10, h0.x, w01);
                fma2(a00, h0.y, w10); fma2(a10, h0.y, w11);
                fma2(a01, h1.x, w00); fma2(a11, h1.x, w01);
                fma2(a01, h1.y, w10); fma2(a11, h1.y, w11);
            }
            __syncthreads();
        }

        // write gates to exchange buffer (+ x-part from G)
        {
            float2 u00 = up2(a00), u10 = up2(a10), u01 = up2(a01), u11 = up2(a11);
            int b0 = 4 * ty;
            Gsm[b0 + 0][r0]     = u00.x + gv[0].x;
            Gsm[b0 + 0][r0 + 1] = u10.x + gv[0].y;
            Gsm[b0 + 1][r0]     = u00.y + gv[1].x;
            Gsm[b0 + 1][r0 + 1] = u10.y + gv[1].y;
            Gsm[b0 + 2][r0]     = u01.x + gv[2].x;
            Gsm[b0 + 2][r0 + 1] = u11.x + gv[2].y;
            Gsm[b0 + 3][r0]     = u01.y + gv[3].x;
            Gsm[b0 + 3][r0 + 1] = u11.y + gv[3].y;
        }
        __syncthreads();

        // pointwise: two (b,h) pairs per thread
        {
            float gi = Gsm[bq0][hh], gf = Gsm[bq0][8 + hh];
            float gg = Gsm[bq0][16 + hh], go = Gsm[bq0][24 + hh];
            float si = 1.f / (1.f + expf(-gi));
            float sf = 1.f / (1.f + expf(-gf));
            float so = 1.f / (1.f + expf(-go));
            c_0 = sf * c_0 + si * tanhf(gg);
            float h = so * tanhf(c_0);
            __stcg(&hnext[(bbase + bq0) * H2_DIM + hidx], h);
            d_Hout[s * B_SZ + bbase + bq0][dir * H2_DIM + hidx] = h;
        }
        {
            int b1 = bq0 + 16;
            float gi = Gsm[b1][hh], gf = Gsm[b1][8 + hh];
            float gg = Gsm[b1][16 + hh], go = Gsm[b1][24 + hh];
            float si = 1.f / (1.f + expf(-gi));
            float sf = 1.f / (1.f + expf(-gf));
            float so = 1.f / (1.f + expf(-go));
            c_1 = sf * c_1 + si * tanhf(gg);
            float h = so * tanhf(c_1);
            __stcg(&hnext[(bbase + b1) * H2_DIM + hidx], h);
            d_Hout[s * B_SZ + bbase + b1][dir * H2_DIM + hidx] = h;
        }

        if (it < S_LEN - 1) {
            // prefetch next step's G BEFORE the barrier (independent of h)
            const int sn = dir ? (S_LEN - 2 - it) : (it + 1);
            float2 gvn[4];
#pragma unroll
            for (int u = 0; u < 4; ++u)
                gvn[u] = *(const float2*)&Gin[(size_t)(sn * B_SZ + bbase + 4 * ty + u) * G4 + rg0];

            // group barrier: release-arrive + acquire-poll on monotonic counter
            __syncthreads();
            if (tid == 0) {
                bar_arrive(grp_cnt);
                const unsigned int target = (unsigned int)(it + 1) * GROUP_BLOCKS;
                while (bar_ld_acq(grp_cnt) < target) { }
            }
            __syncthreads();

#pragma unroll
            for (int u = 0; u < 4; ++u) gv[u] = gvn[u];
        }
    }
}

// ---------------- feats: (16384 x 512) @ (512 x 10) + b ---------------------
__global__ __launch_bounds__(256) void feats_kernel(
    const float* __restrict__ W_out, const float* __restrict__ b_out)
{
    const int warp = threadIdx.x >> 5;
    const int lane = threadIdx.x & 31;
    const int n = blockIdx.x * 8 + warp;
    const float* hrow = &d_Hout[n][0];

    float acc[T_TAGS];
#pragma unroll
    for (int t = 0; t < T_TAGS; ++t) acc[t] = 0.f;

#pragma unroll
    for (int i = 0; i < 16; ++i) {
        int idx = i * 32 + lane;
        float hv = hrow[idx];
#pragma unroll
        for (int t = 0; t < T_TAGS; ++t)
            acc[t] += hv * W_out[t * H_DIM + idx];
    }
#pragma unroll
    for (int t = 0; t < T_TAGS; ++t) {
        float v = acc[t];
#pragma unroll
        for (int off = 16; off > 0; off >>= 1)
            v += __shfl_down_sync(0xffffffffu, v, off);
        if (lane == 0) d_feats[n][t] = v + b_out[t];
    }
}

// ---------------- Viterbi: one warp per batch --------------------------------
// Also resets the lstm barrier counters (stream-ordered after lstm_kernel) so
// the next graph replay starts from zero.
__global__ void viterbi_kernel(const float* __restrict__ trans, float* __restrict__ out) {
    const int b = blockIdx.x;
    const int lane = threadIdx.x;
    __shared__ float tr[T_TAGS][T_TAGS];
    __shared__ unsigned char bp[S_LEN][T_TAGS];

    if (b == 0 && lane < 4) d_cnt[lane * 32] = 0u;

    for (int i = lane; i < T_TAGS * T_TAGS; i += 32)
        tr[i / T_TAGS][i % T_TAGS] = trans[i];
    __syncwarp();

    const int ln = lane < T_TAGS ? lane : 0;   // safe index for lanes >= 10
    float fv = (lane == START_TAG) ? 0.f : -10000.f;

    for (int s = 0; s < S_LEN; ++s) {
        float best = -3.4e38f;
        int arg = 0;
#pragma unroll
        for (int pv = 0; pv < T_TAGS; ++pv) {
            float fp = __shfl_sync(0xffffffffu, fv, pv);
            float v = fp + tr[ln][pv];
            if (v > best) { best = v; arg = pv; }   // strict > keeps FIRST max (jnp.argmax)
        }
        if (lane < T_TAGS) bp[s][lane] = (unsigned char)arg;
        fv = best + d_feats[b * S_LEN + s][ln];
        __syncwarp();
    }

    float term = fv + tr[STOP_TAG][ln];
    __syncwarp();

    float bestv = -3.4e38f;
    int bestt = 0;
#pragma unroll
    for (int t = 0; t < T_TAGS; ++t) {
        float v = __shfl_sync(0xffffffffu, term, t);
        if (v > bestv) { bestv = v; bestt = t; }
    }

    if (lane == 0) {
        out[b] = bestv;                      // path_score (B,1)
        float* pathout = out + B_SZ + b * S_LEN;
        int cur = bestt;
        pathout[S_LEN - 1] = (float)cur;
        for (int s = S_LEN - 2; s >= 0; --s) {
            cur = bp[s + 1][cur];
            pathout[s] = (float)cur;
        }
    }
}

// ---------------- launch ------------------------------------------------------
extern "C" void kernel_launch(void* const* d_in, const int* in_sizes, int n_in,
                              void* d_out, int out_size) {
    const int*   sent  = (const int*)  d_in[0];
    const float* emb   = (const float*)d_in[1];
    const float* wih_f = (const float*)d_in[2];
    const float* whh_f = (const float*)d_in[3];
    const float* bih_f = (const float*)d_in[4];
    const float* bhh_f = (const float*)d_in[5];
    const float* wih_b = (const float*)d_in[6];
    const float* whh_b = (const float*)d_in[7];
    const float* bih_b = (const float*)d_in[8];
    const float* bhh_b = (const float*)d_in[9];
    const float* W_out = (const float*)d_in[10];
    const float* b_out = (const float*)d_in[11];

    // Resolve trailing-argument order at runtime (transitions = 100 elems).
    const float *trans, *h0, *c0;
    if (n_in >= 15 && in_sizes[12] == 100) {
        trans = (const float*)d_in[12];
        h0    = (const float*)d_in[13];
        c0    = (const float*)d_in[14];
    } else {
        h0    = (const float*)d_in[12];
        c0    = (const float*)d_in[13];
        trans = (const float*)d_in[14];
    }

    float* out = (float*)d_out;

    dim3 g(NTOK / 64, G4 / 64, 2);   // 256 x 16 x 2
    input_gemm_kernel<<<g, 256>>>(sent, emb, wih_f, bih_f, bhh_f,
                                  wih_b, bih_b, bhh_b, h0);
    lstm_kernel<<<LSTM_BLOCKS, 128>>>(whh_f, whh_b, c0);
    feats_kernel<<<NTOK / 8, 256>>>(W_out, b_out);
    viterbi_kernel<<<B_SZ, 32>>>(trans, out);
    (void)out_size; (void)n_in;
}